// round 13
// baseline (speedup 1.0000x reference)
#include <cuda_runtime.h>
#include <cuda_bf16.h>

#define NB    4
#define T     4096
#define DIN   1024
#define DHEAD 64
#define MT    (NB*T)
#define PCH   40
#define WP2   80        // interleaved W smem pitch (u32): conflict-free LDS.128

// Q/K planes, fragment-ordered; V transposed
__device__ unsigned g_qb[MT*32], g_qr[MT*32];
__device__ unsigned g_kb[MT*32], g_kr[MT*32];
__device__ unsigned g_vtb[NB*64*(T/2)], g_vtr[NB*64*(T/2)];
// pre-split W, frag-ordered + b/r interleaved: [row 0..191][chunk 0..15][slot*2+plane]
__device__ unsigned g_wp[192*16*64];
// split-K partials
__device__ float g_po[2][MT*DHEAD];
__device__ float g_pl[2][MT];

__device__ __forceinline__ int slotf(int p) {
    return ((p >> 3) << 3) + ((p & 3) << 1) + ((p >> 2) & 1);
}
__device__ __forceinline__ int islot(int s) {
    int w = s & 7;
    return ((s >> 3) << 3) + ((w & 1) ? 4 + (w >> 1) : (w >> 1));
}
__device__ __forceinline__ void mma16816(float&c0,float&c1,float&c2,float&c3,
                                         unsigned a0,unsigned a1,unsigned a2,unsigned a3,
                                         unsigned b0,unsigned b1)
{
    asm volatile("mma.sync.aligned.m16n8k16.row.col.f32.bf16.bf16.f32 "
        "{%0,%1,%2,%3},{%4,%5,%6,%7},{%8,%9},{%0,%1,%2,%3};"
        : "+f"(c0),"+f"(c1),"+f"(c2),"+f"(c3)
        : "r"(a0),"r"(a1),"r"(a2),"r"(a3),"r"(b0),"r"(b1));
}
__device__ __forceinline__ void split2(float lo, float hi, unsigned &b, unsigned &r)
{
    asm("cvt.rn.bf16x2.f32 %0, %1, %2;" : "=r"(b) : "f"(hi), "f"(lo));
    __nv_bfloat162 h2 = *reinterpret_cast<__nv_bfloat162*>(&b);
    float blo = __bfloat162float(h2.x);
    float bhi = __bfloat162float(h2.y);
    asm("cvt.rn.bf16x2.f32 %0, %1, %2;" : "=r"(r) : "f"(hi-bhi), "f"(lo-blo));
}
__device__ __forceinline__ unsigned prmtf(unsigned a, unsigned b, unsigned sel)
{
    unsigned d;
    asm("prmt.b32 %0,%1,%2,%3;" : "=r"(d) : "r"(a), "r"(b), "r"(sel));
    return d;
}
__device__ __forceinline__ void cp16(unsigned dst, const void* src)
{
    asm volatile("cp.async.cg.shared.global [%0],[%1],16;" :: "r"(dst), "l"(src));
}
__device__ __forceinline__ unsigned smem_u32(const void* p)
{
    unsigned a;
    asm("{.reg .u64 t; cvta.to.shared.u64 t, %1; cvt.u32.u64 %0, t;}" : "=r"(a) : "l"(p));
    return a;
}

// ---------------------------------------------------------------------------
// Kernel 0: pre-split W into frag-ordered interleaved planes (runs once, ~2us)
// grid 24, block 256: warp w handles row blk*8+w, 16 chunks.
// ---------------------------------------------------------------------------
__global__ __launch_bounds__(256) void wsplit_kernel(
    const float* __restrict__ Wk, const float* __restrict__ Wq,
    const float* __restrict__ Wv)
{
    const int lane = threadIdx.x & 31;
    const int r    = blockIdx.x * 8 + (threadIdx.x >> 5);   // 0..191
    const int mat  = r >> 6, n = r & 63;
    const float* W = ((mat == 0) ? Wk : (mat == 1) ? Wq : Wv) + (size_t)n * DIN;
    const int p = islot(lane);      // value pair for frag slot = lane
    #pragma unroll
    for (int c = 0; c < 16; c++) {
        float2 v = *(const float2*)&W[c*64 + 2*p];
        unsigned b, rr;
        split2(v.x, v.y, b, rr);
        *(uint2*)&g_wp[(size_t)r*1024 + c*64 + lane*2] = make_uint2(b, rr);
    }
}

// ---------------------------------------------------------------------------
// Kernel 1: FUSED QKV. W via double-buffered cp.async of pre-split planes
// (LDS.128 interleaved fragments); X prefetched to regs, converted once.
// grid MT/128, block 256. smem: W 2 stages @ 192*WP2, then Xb/Xr @ 128*PCH.
// ---------------------------------------------------------------------------
#define WSTG (192*WP2)                         // 15360 u32 per W stage
#define XOFF (2*WSTG)                          // X base (u32)
#define QKV_SMEM ((XOFF + 256*PCH) * 4)        // 163840 B

__global__ __launch_bounds__(256) void qkv_kernel(
    const float* __restrict__ x,
    const float* __restrict__ bk, const float* __restrict__ bq,
    const float* __restrict__ bv)
{
    extern __shared__ unsigned smu[];
    const unsigned sbase = smem_u32(smu);
    unsigned* Xb = smu + XOFF;
    unsigned* Xr = Xb + 128*PCH;

    const int m0   = blockIdx.x * 128;
    const int tid  = threadIdx.x;
    const int lane = tid & 31;
    const int g    = lane >> 2;
    const int q    = lane & 3;
    const int wrow = (tid >> 5) * 16;

    // W producer mapping: 3072 16B segs/chunk, 12 per thread
    #define WISSUE(c, st) do {                                                  \
        _Pragma("unroll")                                                        \
        for (int i_ = 0; i_ < 12; i_++) {                                       \
            int seg_ = tid + 256*i_;                                            \
            int row_ = seg_ >> 4, off_ = seg_ & 15;                             \
            cp16(sbase + ((st)*WSTG + row_*WP2 + off_*4)*4u,                    \
                 g_wp + (size_t)row_*1024 + (c)*64 + off_*4);                   \
        }                                                                        \
        asm volatile("cp.async.commit_group;");                                 \
    } while (0)

    float acc[3][8][4];
    #pragma unroll
    for (int mt = 0; mt < 3; mt++)
        #pragma unroll
        for (int j = 0; j < 8; j++)
            #pragma unroll
            for (int c = 0; c < 4; c++) acc[mt][j][c] = 0.f;

    // prefetch X(0) into regs, issue W(0)
    const int xrow = tid >> 4, xc4 = tid & 15;    // thread's 8 rows: xrow+16*i
    float4 xr4[8];
    WISSUE(0, 0);
    #pragma unroll
    for (int i = 0; i < 8; i++)
        xr4[i] = *(const float4*)&x[(size_t)(m0 + xrow + 16*i)*DIN + 0 + xc4*4];

    for (int c = 0; c < 16; c++) {
        const int st = c & 1;
        if (c < 15) WISSUE(c+1, st^1);
        // convert X(c) from regs to smem
        #pragma unroll
        for (int i = 0; i < 8; i++) {
            unsigned b0,r0,b1,r1;
            split2(xr4[i].x, xr4[i].y, b0, r0);
            split2(xr4[i].z, xr4[i].w, b1, r1);
            int row = xrow + 16*i;
            int s0 = slotf(2*xc4), s1 = slotf(2*xc4+1);
            Xb[row*PCH+s0] = b0;  Xb[row*PCH+s1] = b1;
            Xr[row*PCH+s0] = r0;  Xr[row*PCH+s1] = r1;
        }
        if (c < 15) asm volatile("cp.async.wait_group 1;");
        else        asm volatile("cp.async.wait_group 0;");
        __syncthreads();
        // prefetch X(c+1) into regs (overlaps mma)
        if (c < 15) {
            #pragma unroll
            for (int i = 0; i < 8; i++)
                xr4[i] = *(const float4*)&x[(size_t)(m0 + xrow + 16*i)*DIN + (c+1)*64 + xc4*4];
        }

        const unsigned* Ws = smu + st*WSTG;
        #pragma unroll
        for (int ks = 0; ks < 4; ks++) {
            const int a0 = (wrow+g)*PCH + ks*8 + q*2;
            uint2 xAb = *(const uint2*)&Xb[a0];
            uint2 xBb = *(const uint2*)&Xb[a0 + 8*PCH];
            uint2 xAr = *(const uint2*)&Xr[a0];
            uint2 xBr = *(const uint2*)&Xr[a0 + 8*PCH];
            #pragma unroll
            for (int mt = 0; mt < 3; mt++) {
                #pragma unroll
                for (int jn = 0; jn < 8; jn++) {
                    const int wo = (mt*64 + jn*8 + g)*WP2 + ks*16 + q*4;
                    uint4 w4 = *(const uint4*)&Ws[wo];    // {b0,r0,b1,r1}
                    mma16816(acc[mt][jn][0],acc[mt][jn][1],acc[mt][jn][2],acc[mt][jn][3],
                             xAb.x,xBb.x,xAb.y,xBb.y, w4.x,w4.z);
                    mma16816(acc[mt][jn][0],acc[mt][jn][1],acc[mt][jn][2],acc[mt][jn][3],
                             xAb.x,xBb.x,xAb.y,xBb.y, w4.y,w4.w);
                    mma16816(acc[mt][jn][0],acc[mt][jn][1],acc[mt][jn][2],acc[mt][jn][3],
                             xAr.x,xBr.x,xAr.y,xBr.y, w4.x,w4.z);
                }
            }
        }
        __syncthreads();
    }

    #pragma unroll
    for (int mt = 0; mt < 3; mt++) {
        const float* bias = (mt == 0) ? bk : (mt == 1) ? bq : bv;
        const float qscale = (mt == 1) ? 0.125f : 1.0f;
        #pragma unroll
        for (int jn = 0; jn < 8; jn++) {
            int col = jn*8 + q*2;
            float2 bb = *(const float2*)&bias[col];
            float o0 = fmaxf(acc[mt][jn][0]+bb.x, 0.f) * qscale;
            float o1 = fmaxf(acc[mt][jn][1]+bb.y, 0.f) * qscale;
            float o2 = fmaxf(acc[mt][jn][2]+bb.x, 0.f) * qscale;
            float o3 = fmaxf(acc[mt][jn][3]+bb.y, 0.f) * qscale;
            unsigned vb0, vr0, vb1, vr1;
            split2(o0, o1, vb0, vr0);
            split2(o2, o3, vb1, vr1);

            if (mt != 2) {
                unsigned* pb = (mt == 0) ? g_kb : g_qb;
                unsigned* pr = (mt == 0) ? g_kr : g_qr;
                int sl = slotf(jn*4 + q);
                size_t r0 = (size_t)(m0 + wrow + g);
                pb[r0*32 + sl]     = vb0;  pr[r0*32 + sl]     = vr0;
                pb[(r0+8)*32 + sl] = vb1;  pr[(r0+8)*32 + sl] = vr1;
            } else {
                unsigned ob0 = __shfl_xor_sync(0xffffffffu, vb0, 4);
                unsigned or0 = __shfl_xor_sync(0xffffffffu, vr0, 4);
                unsigned ob1 = __shfl_xor_sync(0xffffffffu, vb1, 4);
                unsigned or1 = __shfl_xor_sync(0xffffffffu, vr1, 4);
                unsigned rb0, rr0, rb1, rr1;
                if ((g & 1) == 0) {
                    rb0 = prmtf(vb0, ob0, 0x5410); rr0 = prmtf(vr0, or0, 0x5410);
                    rb1 = prmtf(vb1, ob1, 0x5410); rr1 = prmtf(vr1, or1, 0x5410);
                } else {
                    rb0 = prmtf(ob0, vb0, 0x7632); rr0 = prmtf(or0, vr0, 0x7632);
                    rb1 = prmtf(ob1, vb1, 0x7632); rr1 = prmtf(or1, vr1, 0x7632);
                }
                int d     = jn*8 + q*2 + (g & 1);
                int brow  = m0 / T;
                int base0 = (m0 & (T-1)) + wrow + (g & ~1);
                int tile  = base0 >> 6;
                int p0    = (base0 & 63) >> 1;
                size_t idx0 = ((size_t)(brow*64 + d))*(T/2) + tile*32 + slotf(p0);
                size_t idx1 = ((size_t)(brow*64 + d))*(T/2) + tile*32 + slotf(p0 + 4);
                g_vtb[idx0] = rb0;  g_vtr[idx0] = rr0;
                g_vtb[idx1] = rb1;  g_vtr[idx1] = rr1;
            }
        }
    }
    #undef WISSUE
}

// ---------------------------------------------------------------------------
// Kernel 2: split-K flash attention (R12, measured). grid (T/128, NB, 2).
// ---------------------------------------------------------------------------
#define ASTAGE (4*64*PCH)
#define ATTN_SMEM (2*ASTAGE*4)

__global__ __launch_bounds__(256, 2) void attn_kernel()
{
    extern __shared__ unsigned smu[];
    const unsigned sbase = smem_u32(smu);

    const int b    = blockIdx.y;
    const int q0   = blockIdx.x * 128;
    const int kh   = blockIdx.z;
    const int kt0  = kh * (T/2);
    const int tid  = threadIdx.x;
    const int lane = tid & 31;
    const int g    = lane >> 2;
    const int q    = lane & 3;
    const int wrow = (tid >> 5) * 16;

    const int arr = tid >> 6;
    const int row = tid & 63;
    const unsigned* src0;
    if      (arr == 0) src0 = g_kb  + ((size_t)(b*T) + row)*32;
    else if (arr == 1) src0 = g_kr  + ((size_t)(b*T) + row)*32;
    else if (arr == 2) src0 = g_vtb + ((size_t)(b*64 + row))*(T/2);
    else               src0 = g_vtr + ((size_t)(b*64 + row))*(T/2);
    const unsigned dstoff = (unsigned)(arr*64*PCH + row*PCH) * 4u;

    #define ISSUE(kt, stg) do {                                                 \
        const unsigned* sp_ = (arr < 2) ? (src0 + (size_t)(kt)*32)              \
                                        : (src0 + (size_t)(kt)/2);              \
        unsigned d_ = sbase + (unsigned)(stg)*ASTAGE*4u + dstoff;               \
        _Pragma("unroll")                                                        \
        for (int i_ = 0; i_ < 8; i_++) cp16(d_ + i_*16u, sp_ + i_*4);           \
    } while (0)

    unsigned qb0[4],qb1[4],qb2[4],qb3[4], qr0[4],qr1[4],qr2[4],qr3[4];
    {
        const size_t r0 = (size_t)(b*T + q0 + wrow + g);
        ISSUE(kt0, 0);
        asm volatile("cp.async.commit_group;");
        #pragma unroll
        for (int ks = 0; ks < 4; ks++) {
            uint2 a  = *(const uint2*)&g_qb[r0*32     + ks*8 + q*2];
            uint2 c  = *(const uint2*)&g_qb[(r0+8)*32 + ks*8 + q*2];
            qb0[ks]=a.x; qb2[ks]=a.y; qb1[ks]=c.x; qb3[ks]=c.y;
            uint2 ar = *(const uint2*)&g_qr[r0*32     + ks*8 + q*2];
            uint2 cr = *(const uint2*)&g_qr[(r0+8)*32 + ks*8 + q*2];
            qr0[ks]=ar.x; qr2[ks]=ar.y; qr1[ks]=cr.x; qr3[ks]=cr.y;
        }
    }

    float oacc[8][4];
    #pragma unroll
    for (int j = 0; j < 8; j++)
        #pragma unroll
        for (int c = 0; c < 4; c++) oacc[j][c] = 0.f;
    float l0 = 0.f, l1 = 0.f;

    int stg = 0;
    for (int i = 0; i < (T/2)/64; i++) {
        const int kt = kt0 + i*64;
        if (i + 1 < (T/2)/64) ISSUE(kt + 64, stg ^ 1);
        asm volatile("cp.async.commit_group;");
        asm volatile("cp.async.wait_group 1;");
        __syncthreads();

        unsigned* Kb = smu + stg*ASTAGE;
        unsigned* Kr = Kb + 64*PCH;
        unsigned* Vb = Kb + 128*PCH;
        unsigned* Vr = Kb + 192*PCH;

        float s[8][4];
        #pragma unroll
        for (int j = 0; j < 8; j++)
            #pragma unroll
            for (int c = 0; c < 4; c++) s[j][c] = 0.f;

        #pragma unroll
        for (int ks = 0; ks < 4; ks++) {
            #pragma unroll
            for (int jn = 0; jn < 8; jn++) {
                const int bbo = (jn*8+g)*PCH + ks*8 + q*2;
                uint2 kb = *(const uint2*)&Kb[bbo];
                uint2 kr = *(const uint2*)&Kr[bbo];
                mma16816(s[jn][0],s[jn][1],s[jn][2],s[jn][3],
                         qb0[ks],qb1[ks],qb2[ks],qb3[ks], kb.x,kb.y);
                mma16816(s[jn][0],s[jn][1],s[jn][2],s[jn][3],
                         qb0[ks],qb1[ks],qb2[ks],qb3[ks], kr.x,kr.y);
                mma16816(s[jn][0],s[jn][1],s[jn][2],s[jn][3],
                         qr0[ks],qr1[ks],qr2[ks],qr3[ks], kb.x,kb.y);
            }
        }

        float sum0 = 0.f, sum1 = 0.f;
        #pragma unroll
        for (int j = 0; j < 8; j++) {
            s[j][0] = __expf(s[j][0] - 16.f);
            s[j][1] = __expf(s[j][1] - 16.f);
            s[j][2] = __expf(s[j][2] - 16.f);
            s[j][3] = __expf(s[j][3] - 16.f);
            sum0 += s[j][0] + s[j][1];
            sum1 += s[j][2] + s[j][3];
        }
        sum0 += __shfl_xor_sync(0xffffffffu, sum0, 1);
        sum0 += __shfl_xor_sync(0xffffffffu, sum0, 2);
        sum1 += __shfl_xor_sync(0xffffffffu, sum1, 1);
        sum1 += __shfl_xor_sync(0xffffffffu, sum1, 2);
        l0 += sum0;
        l1 += sum1;

        #pragma unroll
        for (int kp = 0; kp < 4; kp++) {
            unsigned pb0,pr0,pb1,pr1,pb2,pr2,pb3,pr3;
            split2(s[2*kp  ][0], s[2*kp  ][1], pb0, pr0);
            split2(s[2*kp  ][2], s[2*kp  ][3], pb1, pr1);
            split2(s[2*kp+1][0], s[2*kp+1][1], pb2, pr2);
            split2(s[2*kp+1][2], s[2*kp+1][3], pb3, pr3);
            #pragma unroll
            for (int jn = 0; jn < 8; jn++) {
                const int vbo = (jn*8+g)*PCH + kp*8 + q*2;
                uint2 vb = *(const uint2*)&Vb[vbo];
                uint2 vr = *(const uint2*)&Vr[vbo];
                mma16816(oacc[jn][0],oacc[jn][1],oacc[jn][2],oacc[jn][3],
                         pb0,pb1,pb2,pb3, vb.x,vb.y);
                mma16816(oacc[jn][0],oacc[jn][1],oacc[jn][2],oacc[jn][3],
                         pb0,pb1,pb2,pb3, vr.x,vr.y);
                mma16816(oacc[jn][0],oacc[jn][1],oacc[jn][2],oacc[jn][3],
                         pr0,pr1,pr2,pr3, vb.x,vb.y);
            }
        }
        __syncthreads();
        stg ^= 1;
    }

    float* Og = g_po[kh] + ((size_t)b*T + q0)*DHEAD;
    #pragma unroll
    for (int jn = 0; jn < 8; jn++) {
        int col = jn*8 + q*2;
        int r0 = wrow + g;
        *(float2*)&Og[(size_t)r0*DHEAD + col]     = make_float2(oacc[jn][0], oacc[jn][1]);
        *(float2*)&Og[(size_t)(r0+8)*DHEAD + col] = make_float2(oacc[jn][2], oacc[jn][3]);
    }
    if (q == 0) {
        g_pl[kh][(size_t)b*T + q0 + wrow + g]     = l0;
        g_pl[kh][(size_t)b*T + q0 + wrow + 8 + g] = l1;
    }
    #undef ISSUE
}

// ---------------------------------------------------------------------------
// Kernel 3: merge split-K partials.
// ---------------------------------------------------------------------------
__global__ __launch_bounds__(256) void merge_kernel(float* __restrict__ out)
{
    const int idx4 = blockIdx.x * 256 + threadIdx.x;
    const size_t base = (size_t)idx4 * 4;
    const int row = (int)(base >> 6);
    float4 a = *(const float4*)&g_po[0][base];
    float4 b = *(const float4*)&g_po[1][base];
    float inv = 1.f / (g_pl[0][row] + g_pl[1][row]);
    float4 o;
    o.x = (a.x + b.x) * inv;
    o.y = (a.y + b.y) * inv;
    o.z = (a.z + b.z) * inv;
    o.w = (a.w + b.w) * inv;
    *(float4*)&out[base] = o;
}

// ---------------------------------------------------------------------------
extern "C" void kernel_launch(void* const* d_in, const int* in_sizes, int n_in,
                              void* d_out, int out_size)
{
    const float* x  = (const float*)d_in[0];
    const float* Wk = (const float*)d_in[1];
    const float* bk = (const float*)d_in[2];
    const float* Wq = (const float*)d_in[3];
    const float* bq = (const float*)d_in[4];
    const float* Wv = (const float*)d_in[5];
    const float* bv = (const float*)d_in[6];
    float* out = (float*)d_out;

    cudaFuncSetAttribute(qkv_kernel,
                         cudaFuncAttributeMaxDynamicSharedMemorySize, QKV_SMEM);
    cudaFuncSetAttribute(attn_kernel,
                         cudaFuncAttributeMaxDynamicSharedMemorySize, ATTN_SMEM);

    wsplit_kernel<<<24, 256>>>(Wk, Wq, Wv);
    qkv_kernel<<<MT/128, 256, QKV_SMEM>>>(x, bk, bq, bv);

    dim3 g2(T / 128, NB, 2);
    attn_kernel<<<g2, 256, ATTN_SMEM>>>();

    merge_kernel<<<(MT*DHEAD/4)/256, 256>>>(out);
}

// round 15
// speedup vs baseline: 1.3389x; 1.3389x over previous
#include <cuda_runtime.h>
#include <cuda_bf16.h>

#define NB    4
#define T     4096
#define DIN   1024
#define DHEAD 64
#define MT    (NB*T)
#define PCH   40

// Q/K planes, fragment-ordered; V transposed (bf16 only, no residual plane)
__device__ unsigned g_qb[MT*32], g_qr[MT*32];
__device__ unsigned g_kb[MT*32], g_kr[MT*32];
__device__ unsigned g_vtb[NB*64*(T/2)];
// split-K partials
__device__ float g_po[2][MT*DHEAD];
__device__ float g_pl[2][MT];

__device__ __forceinline__ int slotf(int p) {
    return ((p >> 3) << 3) + ((p & 3) << 1) + ((p >> 2) & 1);
}
__device__ __forceinline__ void mma16816(float&c0,float&c1,float&c2,float&c3,
                                         unsigned a0,unsigned a1,unsigned a2,unsigned a3,
                                         unsigned b0,unsigned b1)
{
    asm volatile("mma.sync.aligned.m16n8k16.row.col.f32.bf16.bf16.f32 "
        "{%0,%1,%2,%3},{%4,%5,%6,%7},{%8,%9},{%0,%1,%2,%3};"
        : "+f"(c0),"+f"(c1),"+f"(c2),"+f"(c3)
        : "r"(a0),"r"(a1),"r"(a2),"r"(a3),"r"(b0),"r"(b1));
}
__device__ __forceinline__ void split2(float lo, float hi, unsigned &b, unsigned &r)
{
    asm("cvt.rn.bf16x2.f32 %0, %1, %2;" : "=r"(b) : "f"(hi), "f"(lo));
    __nv_bfloat162 h2 = *reinterpret_cast<__nv_bfloat162*>(&b);
    float blo = __bfloat162float(h2.x);
    float bhi = __bfloat162float(h2.y);
    asm("cvt.rn.bf16x2.f32 %0, %1, %2;" : "=r"(r) : "f"(hi-bhi), "f"(lo-blo));
}
__device__ __forceinline__ unsigned pack2(float lo, float hi)
{
    unsigned d;
    asm("cvt.rn.bf16x2.f32 %0, %1, %2;" : "=r"(d) : "f"(hi), "f"(lo));
    return d;
}
__device__ __forceinline__ unsigned prmtf(unsigned a, unsigned b, unsigned sel)
{
    unsigned d;
    asm("prmt.b32 %0,%1,%2,%3;" : "=r"(d) : "r"(a), "r"(b), "r"(sel));
    return d;
}
__device__ __forceinline__ void cp16(unsigned dst, const void* src)
{
    asm volatile("cp.async.cg.shared.global [%0],[%1],16;" :: "r"(dst), "l"(src));
}
__device__ __forceinline__ unsigned smem_u32(const void* p)
{
    unsigned a;
    asm("{.reg .u64 t; cvta.to.shared.u64 t, %1; cvt.u32.u64 %0, t;}" : "=r"(a) : "l"(p));
    return a;
}

// ---------------------------------------------------------------------------
// Kernel 1: FUSED QKV projection (R12 version, measured 91us).
// ---------------------------------------------------------------------------
#define QKV_SMEM (640 * PCH * 4)

__global__ __launch_bounds__(256) void qkv_kernel(
    const float* __restrict__ x,
    const float* __restrict__ Wk, const float* __restrict__ bk,
    const float* __restrict__ Wq, const float* __restrict__ bq,
    const float* __restrict__ Wv, const float* __restrict__ bv)
{
    extern __shared__ unsigned smu[];
    unsigned* Xb = smu;
    unsigned* Xr = Xb + 128*PCH;
    unsigned* Wb = Xr + 128*PCH;
    unsigned* Wr = Wb + 192*PCH;

    const int m0   = blockIdx.x * 128;
    const int tid  = threadIdx.x;
    const int lane = tid & 31;
    const int g    = lane >> 2;
    const int q    = lane & 3;
    const int wrow = (tid >> 5) * 16;

    float acc[3][8][4];
    #pragma unroll
    for (int mt = 0; mt < 3; mt++)
        #pragma unroll
        for (int j = 0; j < 8; j++)
            #pragma unroll
            for (int c = 0; c < 4; c++) acc[mt][j][c] = 0.f;

    for (int kc = 0; kc < DIN; kc += 64) {
        __syncthreads();
        #pragma unroll
        for (int i = 0; i < 8; i++) {
            int idx = tid + 256*i;
            int row = idx >> 4, c4 = idx & 15;
            float4 v = *(const float4*)&x[(size_t)(m0+row)*DIN + kc + c4*4];
            unsigned b0,r0,b1,r1;
            split2(v.x, v.y, b0, r0);
            split2(v.z, v.w, b1, r1);
            int s0 = slotf(2*c4), s1 = slotf(2*c4+1);
            Xb[row*PCH+s0] = b0;  Xb[row*PCH+s1] = b1;
            Xr[row*PCH+s0] = r0;  Xr[row*PCH+s1] = r1;
        }
        #pragma unroll
        for (int i = 0; i < 12; i++) {
            int idx = tid + 256*i;
            int row = idx >> 4, c4 = idx & 15;
            int mt = row >> 6, n = row & 63;
            const float* W = (mt == 0) ? Wk : (mt == 1) ? Wq : Wv;
            float4 v = *(const float4*)&W[(size_t)n*DIN + kc + c4*4];
            unsigned b0,r0,b1,r1;
            split2(v.x, v.y, b0, r0);
            split2(v.z, v.w, b1, r1);
            int s0 = slotf(2*c4), s1 = slotf(2*c4+1);
            Wb[row*PCH+s0] = b0;  Wb[row*PCH+s1] = b1;
            Wr[row*PCH+s0] = r0;  Wr[row*PCH+s1] = r1;
        }
        __syncthreads();

        #pragma unroll
        for (int ks = 0; ks < 4; ks++) {
            const int a0 = (wrow+g)*PCH + ks*8 + q*2;
            uint2 xAb = *(const uint2*)&Xb[a0];
            uint2 xBb = *(const uint2*)&Xb[a0 + 8*PCH];
            uint2 xAr = *(const uint2*)&Xr[a0];
            uint2 xBr = *(const uint2*)&Xr[a0 + 8*PCH];
            #pragma unroll
            for (int mt = 0; mt < 3; mt++) {
                #pragma unroll
                for (int jn = 0; jn < 8; jn++) {
                    const int bbo = (mt*64 + jn*8 + g)*PCH + ks*8 + q*2;
                    uint2 wb = *(const uint2*)&Wb[bbo];
                    uint2 wr = *(const uint2*)&Wr[bbo];
                    mma16816(acc[mt][jn][0],acc[mt][jn][1],acc[mt][jn][2],acc[mt][jn][3],
                             xAb.x,xBb.x,xAb.y,xBb.y, wb.x,wb.y);
                    mma16816(acc[mt][jn][0],acc[mt][jn][1],acc[mt][jn][2],acc[mt][jn][3],
                             xAb.x,xBb.x,xAb.y,xBb.y, wr.x,wr.y);
                    mma16816(acc[mt][jn][0],acc[mt][jn][1],acc[mt][jn][2],acc[mt][jn][3],
                             xAr.x,xBr.x,xAr.y,xBr.y, wb.x,wb.y);
                }
            }
        }
    }

    #pragma unroll
    for (int mt = 0; mt < 3; mt++) {
        const float* bias = (mt == 0) ? bk : (mt == 1) ? bq : bv;
        const float qscale = (mt == 1) ? 0.125f : 1.0f;
        #pragma unroll
        for (int jn = 0; jn < 8; jn++) {
            int col = jn*8 + q*2;
            float2 bb = *(const float2*)&bias[col];
            float o0 = fmaxf(acc[mt][jn][0]+bb.x, 0.f) * qscale;
            float o1 = fmaxf(acc[mt][jn][1]+bb.y, 0.f) * qscale;
            float o2 = fmaxf(acc[mt][jn][2]+bb.x, 0.f) * qscale;
            float o3 = fmaxf(acc[mt][jn][3]+bb.y, 0.f) * qscale;

            if (mt != 2) {
                unsigned vb0, vr0, vb1, vr1;
                split2(o0, o1, vb0, vr0);
                split2(o2, o3, vb1, vr1);
                unsigned* pb = (mt == 0) ? g_kb : g_qb;
                unsigned* pr = (mt == 0) ? g_kr : g_qr;
                int sl = slotf(jn*4 + q);
                size_t r0 = (size_t)(m0 + wrow + g);
                pb[r0*32 + sl]     = vb0;  pr[r0*32 + sl]     = vr0;
                pb[(r0+8)*32 + sl] = vb1;  pr[(r0+8)*32 + sl] = vr1;
            } else {
                // V: bf16 only (PV runs pure bf16); transpose via shfl+prmt
                unsigned vb0 = pack2(o0, o1);
                unsigned vb1 = pack2(o2, o3);
                unsigned ob0 = __shfl_xor_sync(0xffffffffu, vb0, 4);
                unsigned ob1 = __shfl_xor_sync(0xffffffffu, vb1, 4);
                unsigned rb0, rb1;
                if ((g & 1) == 0) {
                    rb0 = prmtf(vb0, ob0, 0x5410);
                    rb1 = prmtf(vb1, ob1, 0x5410);
                } else {
                    rb0 = prmtf(ob0, vb0, 0x7632);
                    rb1 = prmtf(ob1, vb1, 0x7632);
                }
                int d     = jn*8 + q*2 + (g & 1);
                int brow  = m0 / T;
                int base0 = (m0 & (T-1)) + wrow + (g & ~1);
                int tile  = base0 >> 6;
                int p0    = (base0 & 63) >> 1;
                size_t idx0 = ((size_t)(brow*64 + d))*(T/2) + tile*32 + slotf(p0);
                size_t idx1 = ((size_t)(brow*64 + d))*(T/2) + tile*32 + slotf(p0 + 4);
                g_vtb[idx0] = rb0;
                g_vtb[idx1] = rb1;
            }
        }
    }
}

// ---------------------------------------------------------------------------
// Kernel 2: split-K flash attention, pure-bf16 PV (positive weights).
// Stage: Kb, Kr, Vb (192 rows @ PCH). grid (T/128, NB, 2), 2 CTAs/SM.
// ---------------------------------------------------------------------------
#define ASTAGE (3*64*PCH)
#define ATTN_SMEM (2*ASTAGE*4)          // 61440 B

__global__ __launch_bounds__(256, 2) void attn_kernel()
{
    extern __shared__ unsigned smu[];
    const unsigned sbase = smem_u32(smu);

    const int b    = blockIdx.y;
    const int q0   = blockIdx.x * 128;
    const int kh   = blockIdx.z;
    const int kt0  = kh * (T/2);
    const int tid  = threadIdx.x;
    const int lane = tid & 31;
    const int g    = lane >> 2;
    const int q    = lane & 3;
    const int wrow = (tid >> 5) * 16;

    // producers: 192 rows, threads 0..191 take one row each
    const int arr = tid >> 6;            // 0..3; arr==3 idle
    const int row = tid & 63;
    const unsigned* src0 = g_kb;
    if      (arr == 1) src0 = g_kr  + ((size_t)(b*T) + row)*32;
    else if (arr == 2) src0 = g_vtb + ((size_t)(b*64 + row))*(T/2);
    else               src0 = g_kb  + ((size_t)(b*T) + row)*32;
    const unsigned dstoff = (unsigned)(arr*64*PCH + row*PCH) * 4u;

    #define ISSUE(kt, stg) do {                                                 \
        if (arr < 3) {                                                          \
            const unsigned* sp_ = (arr < 2) ? (src0 + (size_t)(kt)*32)          \
                                            : (src0 + (size_t)(kt)/2);          \
            unsigned d_ = sbase + (unsigned)(stg)*ASTAGE*4u + dstoff;           \
            _Pragma("unroll")                                                    \
            for (int i_ = 0; i_ < 8; i_++) cp16(d_ + i_*16u, sp_ + i_*4);       \
        }                                                                        \
    } while (0)

    unsigned qb0[4],qb1[4],qb2[4],qb3[4], qr0[4],qr1[4],qr2[4],qr3[4];
    {
        const size_t r0 = (size_t)(b*T + q0 + wrow + g);
        ISSUE(kt0, 0);
        asm volatile("cp.async.commit_group;");
        #pragma unroll
        for (int ks = 0; ks < 4; ks++) {
            uint2 a  = *(const uint2*)&g_qb[r0*32     + ks*8 + q*2];
            uint2 c  = *(const uint2*)&g_qb[(r0+8)*32 + ks*8 + q*2];
            qb0[ks]=a.x; qb2[ks]=a.y; qb1[ks]=c.x; qb3[ks]=c.y;
            uint2 ar = *(const uint2*)&g_qr[r0*32     + ks*8 + q*2];
            uint2 cr = *(const uint2*)&g_qr[(r0+8)*32 + ks*8 + q*2];
            qr0[ks]=ar.x; qr2[ks]=ar.y; qr1[ks]=cr.x; qr3[ks]=cr.y;
        }
    }

    float oacc[8][4];
    #pragma unroll
    for (int j = 0; j < 8; j++)
        #pragma unroll
        for (int c = 0; c < 4; c++) oacc[j][c] = 0.f;
    float l0 = 0.f, l1 = 0.f;

    int stg = 0;
    for (int i = 0; i < (T/2)/64; i++) {
        const int kt = kt0 + i*64;
        if (i + 1 < (T/2)/64) ISSUE(kt + 64, stg ^ 1);
        asm volatile("cp.async.commit_group;");
        asm volatile("cp.async.wait_group 1;");
        __syncthreads();

        unsigned* Kb = smu + stg*ASTAGE;
        unsigned* Kr = Kb + 64*PCH;
        unsigned* Vb = Kb + 128*PCH;

        float s[8][4];
        #pragma unroll
        for (int j = 0; j < 8; j++)
            #pragma unroll
            for (int c = 0; c < 4; c++) s[j][c] = 0.f;

        #pragma unroll
        for (int ks = 0; ks < 4; ks++) {
            #pragma unroll
            for (int jn = 0; jn < 8; jn++) {
                const int bbo = (jn*8+g)*PCH + ks*8 + q*2;
                uint2 kb = *(const uint2*)&Kb[bbo];
                uint2 kr = *(const uint2*)&Kr[bbo];
                mma16816(s[jn][0],s[jn][1],s[jn][2],s[jn][3],
                         qb0[ks],qb1[ks],qb2[ks],qb3[ks], kb.x,kb.y);
                mma16816(s[jn][0],s[jn][1],s[jn][2],s[jn][3],
                         qb0[ks],qb1[ks],qb2[ks],qb3[ks], kr.x,kr.y);
                mma16816(s[jn][0],s[jn][1],s[jn][2],s[jn][3],
                         qr0[ks],qr1[ks],qr2[ks],qr3[ks], kb.x,kb.y);
            }
        }

        // fixed-shift softmax: p = exp(s - 16)
        float sum0 = 0.f, sum1 = 0.f;
        #pragma unroll
        for (int j = 0; j < 8; j++) {
            s[j][0] = __expf(s[j][0] - 16.f);
            s[j][1] = __expf(s[j][1] - 16.f);
            s[j][2] = __expf(s[j][2] - 16.f);
            s[j][3] = __expf(s[j][3] - 16.f);
            sum0 += s[j][0] + s[j][1];
            sum1 += s[j][2] + s[j][3];
        }
        sum0 += __shfl_xor_sync(0xffffffffu, sum0, 1);
        sum0 += __shfl_xor_sync(0xffffffffu, sum0, 2);
        sum1 += __shfl_xor_sync(0xffffffffu, sum1, 1);
        sum1 += __shfl_xor_sync(0xffffffffu, sum1, 2);
        l0 += sum0;
        l1 += sum1;

        // O += P V (pure bf16: p,v >= 0, rounding averages out)
        #pragma unroll
        for (int kp = 0; kp < 4; kp++) {
            unsigned pb0 = pack2(s[2*kp  ][0], s[2*kp  ][1]);
            unsigned pb1 = pack2(s[2*kp  ][2], s[2*kp  ][3]);
            unsigned pb2 = pack2(s[2*kp+1][0], s[2*kp+1][1]);
            unsigned pb3 = pack2(s[2*kp+1][2], s[2*kp+1][3]);
            #pragma unroll
            for (int jn = 0; jn < 8; jn++) {
                const int vbo = (jn*8+g)*PCH + kp*8 + q*2;
                uint2 vb = *(const uint2*)&Vb[vbo];
                mma16816(oacc[jn][0],oacc[jn][1],oacc[jn][2],oacc[jn][3],
                         pb0,pb1,pb2,pb3, vb.x,vb.y);
            }
        }
        __syncthreads();
        stg ^= 1;
    }

    float* Og = g_po[kh] + ((size_t)b*T + q0)*DHEAD;
    #pragma unroll
    for (int jn = 0; jn < 8; jn++) {
        int col = jn*8 + q*2;
        int r0 = wrow + g;
        *(float2*)&Og[(size_t)r0*DHEAD + col]     = make_float2(oacc[jn][0], oacc[jn][1]);
        *(float2*)&Og[(size_t)(r0+8)*DHEAD + col] = make_float2(oacc[jn][2], oacc[jn][3]);
    }
    if (q == 0) {
        g_pl[kh][(size_t)b*T + q0 + wrow + g]     = l0;
        g_pl[kh][(size_t)b*T + q0 + wrow + 8 + g] = l1;
    }
    #undef ISSUE
}

// ---------------------------------------------------------------------------
// Kernel 3: merge split-K partials. out = (Oa + Ob) / (la + lb).
// ---------------------------------------------------------------------------
__global__ __launch_bounds__(256) void merge_kernel(float* __restrict__ out)
{
    const int idx4 = blockIdx.x * 256 + threadIdx.x;
    const size_t base = (size_t)idx4 * 4;
    const int row = (int)(base >> 6);
    float4 a = *(const float4*)&g_po[0][base];
    float4 b = *(const float4*)&g_po[1][base];
    float inv = 1.f / (g_pl[0][row] + g_pl[1][row]);
    float4 o;
    o.x = (a.x + b.x) * inv;
    o.y = (a.y + b.y) * inv;
    o.z = (a.z + b.z) * inv;
    o.w = (a.w + b.w) * inv;
    *(float4*)&out[base] = o;
}

// ---------------------------------------------------------------------------
extern "C" void kernel_launch(void* const* d_in, const int* in_sizes, int n_in,
                              void* d_out, int out_size)
{
    const float* x  = (const float*)d_in[0];
    const float* Wk = (const float*)d_in[1];
    const float* bk = (const float*)d_in[2];
    const float* Wq = (const float*)d_in[3];
    const float* bq = (const float*)d_in[4];
    const float* Wv = (const float*)d_in[5];
    const float* bv = (const float*)d_in[6];
    float* out = (float*)d_out;

    cudaFuncSetAttribute(qkv_kernel,
                         cudaFuncAttributeMaxDynamicSharedMemorySize, QKV_SMEM);
    cudaFuncSetAttribute(attn_kernel,
                         cudaFuncAttributeMaxDynamicSharedMemorySize, ATTN_SMEM);

    qkv_kernel<<<MT/128, 256, QKV_SMEM>>>(x, Wk, bk, Wq, bq, Wv, bv);

    dim3 g2(T / 128, NB, 2);
    attn_kernel<<<g2, 256, ATTN_SMEM>>>();

    merge_kernel<<<(MT*DHEAD/4)/256, 256>>>(out);
}

// round 17
// speedup vs baseline: 2.0544x; 1.5344x over previous
#include <cuda_runtime.h>
#include <cuda_bf16.h>

#define NB    4
#define T     4096
#define DIN   1024
#define DHEAD 64
#define MT    (NB*T)
#define PCH   40

// Q/K planes (bf16, fragment-ordered); V transposed (bf16)
__device__ unsigned g_qb[MT*32];
__device__ unsigned g_kb[MT*32];
__device__ unsigned g_vtb[NB*64*(T/2)];
// split-K partials
__device__ float g_po[2][MT*DHEAD];
__device__ float g_pl[2][MT];

__device__ __forceinline__ int slotf(int p) {
    return ((p >> 3) << 3) + ((p & 3) << 1) + ((p >> 2) & 1);
}
__device__ __forceinline__ void mma16816(float&c0,float&c1,float&c2,float&c3,
                                         unsigned a0,unsigned a1,unsigned a2,unsigned a3,
                                         unsigned b0,unsigned b1)
{
    asm volatile("mma.sync.aligned.m16n8k16.row.col.f32.bf16.bf16.f32 "
        "{%0,%1,%2,%3},{%4,%5,%6,%7},{%8,%9},{%0,%1,%2,%3};"
        : "+f"(c0),"+f"(c1),"+f"(c2),"+f"(c3)
        : "r"(a0),"r"(a1),"r"(a2),"r"(a3),"r"(b0),"r"(b1));
}
__device__ __forceinline__ unsigned pack2(float lo, float hi)
{
    unsigned d;
    asm("cvt.rn.bf16x2.f32 %0, %1, %2;" : "=r"(d) : "f"(hi), "f"(lo));
    return d;
}
__device__ __forceinline__ unsigned prmtf(unsigned a, unsigned b, unsigned sel)
{
    unsigned d;
    asm("prmt.b32 %0,%1,%2,%3;" : "=r"(d) : "r"(a), "r"(b), "r"(sel));
    return d;
}
__device__ __forceinline__ void cp16(unsigned dst, const void* src)
{
    asm volatile("cp.async.cg.shared.global [%0],[%1],16;" :: "r"(dst), "l"(src));
}
__device__ __forceinline__ unsigned smem_u32(const void* p)
{
    unsigned a;
    asm("{.reg .u64 t; cvta.to.shared.u64 t, %1; cvt.u32.u64 %0, t;}" : "=r"(a) : "l"(p));
    return a;
}

// ---------------------------------------------------------------------------
// Kernel 1: FUSED QKV projection, pure bf16. grid MT/128, block 256.
// smem: Xb[128 rows], Wb[192 rows] @ pitch PCH = 51200 B.
// ---------------------------------------------------------------------------
#define QKV_SMEM (320 * PCH * 4)

__global__ __launch_bounds__(256) void qkv_kernel(
    const float* __restrict__ x,
    const float* __restrict__ Wk, const float* __restrict__ bk,
    const float* __restrict__ Wq, const float* __restrict__ bq,
    const float* __restrict__ Wv, const float* __restrict__ bv)
{
    extern __shared__ unsigned smu[];
    unsigned* Xb = smu;
    unsigned* Wb = Xb + 128*PCH;           // rows: mat*64 + n

    const int m0   = blockIdx.x * 128;
    const int tid  = threadIdx.x;
    const int lane = tid & 31;
    const int g    = lane >> 2;
    const int q    = lane & 3;
    const int wrow = (tid >> 5) * 16;

    float acc[3][8][4];
    #pragma unroll
    for (int mt = 0; mt < 3; mt++)
        #pragma unroll
        for (int j = 0; j < 8; j++)
            #pragma unroll
            for (int c = 0; c < 4; c++) acc[mt][j][c] = 0.f;

    for (int kc = 0; kc < DIN; kc += 64) {
        __syncthreads();
        // X tile: 128 rows x 64 cols
        #pragma unroll
        for (int i = 0; i < 8; i++) {
            int idx = tid + 256*i;
            int row = idx >> 4, c4 = idx & 15;
            float4 v = *(const float4*)&x[(size_t)(m0+row)*DIN + kc + c4*4];
            Xb[row*PCH + slotf(2*c4)]   = pack2(v.x, v.y);
            Xb[row*PCH + slotf(2*c4+1)] = pack2(v.z, v.w);
        }
        // W tiles for 3 mats: 192 rows x 64 cols
        #pragma unroll
        for (int i = 0; i < 12; i++) {
            int idx = tid + 256*i;
            int row = idx >> 4, c4 = idx & 15;
            int mt = row >> 6, n = row & 63;
            const float* W = (mt == 0) ? Wk : (mt == 1) ? Wq : Wv;
            float4 v = *(const float4*)&W[(size_t)n*DIN + kc + c4*4];
            Wb[row*PCH + slotf(2*c4)]   = pack2(v.x, v.y);
            Wb[row*PCH + slotf(2*c4+1)] = pack2(v.z, v.w);
        }
        __syncthreads();

        #pragma unroll
        for (int ks = 0; ks < 4; ks++) {
            const int a0 = (wrow+g)*PCH + ks*8 + q*2;
            uint2 xA = *(const uint2*)&Xb[a0];
            uint2 xB = *(const uint2*)&Xb[a0 + 8*PCH];
            #pragma unroll
            for (int mt = 0; mt < 3; mt++) {
                #pragma unroll
                for (int jn = 0; jn < 8; jn++) {
                    const int bbo = (mt*64 + jn*8 + g)*PCH + ks*8 + q*2;
                    uint2 wb = *(const uint2*)&Wb[bbo];
                    mma16816(acc[mt][jn][0],acc[mt][jn][1],acc[mt][jn][2],acc[mt][jn][3],
                             xA.x,xB.x,xA.y,xB.y, wb.x,wb.y);
                }
            }
        }
    }

    #pragma unroll
    for (int mt = 0; mt < 3; mt++) {
        const float* bias = (mt == 0) ? bk : (mt == 1) ? bq : bv;
        const float qscale = (mt == 1) ? 0.125f : 1.0f;
        #pragma unroll
        for (int jn = 0; jn < 8; jn++) {
            int col = jn*8 + q*2;
            float2 bb = *(const float2*)&bias[col];
            float o0 = fmaxf(acc[mt][jn][0]+bb.x, 0.f) * qscale;
            float o1 = fmaxf(acc[mt][jn][1]+bb.y, 0.f) * qscale;
            float o2 = fmaxf(acc[mt][jn][2]+bb.x, 0.f) * qscale;
            float o3 = fmaxf(acc[mt][jn][3]+bb.y, 0.f) * qscale;
            unsigned vb0 = pack2(o0, o1);
            unsigned vb1 = pack2(o2, o3);

            if (mt != 2) {
                unsigned* pb = (mt == 0) ? g_kb : g_qb;
                int sl = slotf(jn*4 + q);
                size_t r0 = (size_t)(m0 + wrow + g);
                pb[r0*32 + sl]     = vb0;
                pb[(r0+8)*32 + sl] = vb1;
            } else {
                // V: transpose to key-pair u32 via shfl+prmt
                unsigned ob0 = __shfl_xor_sync(0xffffffffu, vb0, 4);
                unsigned ob1 = __shfl_xor_sync(0xffffffffu, vb1, 4);
                unsigned rb0, rb1;
                if ((g & 1) == 0) {
                    rb0 = prmtf(vb0, ob0, 0x5410);
                    rb1 = prmtf(vb1, ob1, 0x5410);
                } else {
                    rb0 = prmtf(ob0, vb0, 0x7632);
                    rb1 = prmtf(ob1, vb1, 0x7632);
                }
                int d     = jn*8 + q*2 + (g & 1);
                int brow  = m0 / T;
                int base0 = (m0 & (T-1)) + wrow + (g & ~1);
                int tile  = base0 >> 6;
                int p0    = (base0 & 63) >> 1;
                size_t idx0 = ((size_t)(brow*64 + d))*(T/2) + tile*32 + slotf(p0);
                size_t idx1 = ((size_t)(brow*64 + d))*(T/2) + tile*32 + slotf(p0 + 4);
                g_vtb[idx0] = rb0;
                g_vtb[idx1] = rb1;
            }
        }
    }
}

// ---------------------------------------------------------------------------
// Kernel 2: split-K flash attention, pure bf16 QK and PV.
// Stage: Kb, Vb (128 rows @ PCH = 20 KB). grid (T/128, NB, 2), 2 CTAs/SM.
// ---------------------------------------------------------------------------
#define ASTAGE (2*64*PCH)
#define ATTN_SMEM (2*ASTAGE*4)          // 40960 B

__global__ __launch_bounds__(256, 2) void attn_kernel()
{
    extern __shared__ unsigned smu[];
    const unsigned sbase = smem_u32(smu);

    const int b    = blockIdx.y;
    const int q0   = blockIdx.x * 128;
    const int kh   = blockIdx.z;
    const int kt0  = kh * (T/2);
    const int tid  = threadIdx.x;
    const int lane = tid & 31;
    const int g    = lane >> 2;
    const int q    = lane & 3;
    const int wrow = (tid >> 5) * 16;

    // producers: 128 rows (Kb, Vtb x 64), threads 0..127
    const int arr = tid >> 6;            // 0,1 active; 2,3 idle
    const int row = tid & 63;
    const unsigned* src0;
    if (arr == 0) src0 = g_kb  + ((size_t)(b*T) + row)*32;
    else          src0 = g_vtb + ((size_t)(b*64 + row))*(T/2);
    const unsigned dstoff = (unsigned)(arr*64*PCH + row*PCH) * 4u;

    #define ISSUE(kt, stg) do {                                                 \
        if (arr < 2) {                                                          \
            const unsigned* sp_ = (arr == 0) ? (src0 + (size_t)(kt)*32)         \
                                             : (src0 + (size_t)(kt)/2);         \
            unsigned d_ = sbase + (unsigned)(stg)*ASTAGE*4u + dstoff;           \
            _Pragma("unroll")                                                    \
            for (int i_ = 0; i_ < 8; i_++) cp16(d_ + i_*16u, sp_ + i_*4);       \
        }                                                                        \
    } while (0)

    unsigned qb0[4],qb1[4],qb2[4],qb3[4];
    {
        const size_t r0 = (size_t)(b*T + q0 + wrow + g);
        ISSUE(kt0, 0);
        asm volatile("cp.async.commit_group;");
        #pragma unroll
        for (int ks = 0; ks < 4; ks++) {
            uint2 a  = *(const uint2*)&g_qb[r0*32     + ks*8 + q*2];
            uint2 c  = *(const uint2*)&g_qb[(r0+8)*32 + ks*8 + q*2];
            qb0[ks]=a.x; qb2[ks]=a.y; qb1[ks]=c.x; qb3[ks]=c.y;
        }
    }

    float oacc[8][4];
    #pragma unroll
    for (int j = 0; j < 8; j++)
        #pragma unroll
        for (int c = 0; c < 4; c++) oacc[j][c] = 0.f;
    float l0 = 0.f, l1 = 0.f;

    int stg = 0;
    for (int i = 0; i < (T/2)/64; i++) {
        const int kt = kt0 + i*64;
        if (i + 1 < (T/2)/64) ISSUE(kt + 64, stg ^ 1);
        asm volatile("cp.async.commit_group;");
        asm volatile("cp.async.wait_group 1;");
        __syncthreads();

        unsigned* Kb = smu + stg*ASTAGE;
        unsigned* Vb = Kb + 64*PCH;

        float s[8][4];
        #pragma unroll
        for (int j = 0; j < 8; j++)
            #pragma unroll
            for (int c = 0; c < 4; c++) s[j][c] = 0.f;

        #pragma unroll
        for (int ks = 0; ks < 4; ks++) {
            #pragma unroll
            for (int jn = 0; jn < 8; jn++) {
                const int bbo = (jn*8+g)*PCH + ks*8 + q*2;
                uint2 kb = *(const uint2*)&Kb[bbo];
                mma16816(s[jn][0],s[jn][1],s[jn][2],s[jn][3],
                         qb0[ks],qb1[ks],qb2[ks],qb3[ks], kb.x,kb.y);
            }
        }

        // fixed-shift softmax: p = exp(s - 16); s >= 0 (ReLU'd q,k)
        float sum0 = 0.f, sum1 = 0.f;
        #pragma unroll
        for (int j = 0; j < 8; j++) {
            s[j][0] = __expf(s[j][0] - 16.f);
            s[j][1] = __expf(s[j][1] - 16.f);
            s[j][2] = __expf(s[j][2] - 16.f);
            s[j][3] = __expf(s[j][3] - 16.f);
            sum0 += s[j][0] + s[j][1];
            sum1 += s[j][2] + s[j][3];
        }
        sum0 += __shfl_xor_sync(0xffffffffu, sum0, 1);
        sum0 += __shfl_xor_sync(0xffffffffu, sum0, 2);
        sum1 += __shfl_xor_sync(0xffffffffu, sum1, 1);
        sum1 += __shfl_xor_sync(0xffffffffu, sum1, 2);
        l0 += sum0;
        l1 += sum1;

        // O += P V (pure bf16)
        #pragma unroll
        for (int kp = 0; kp < 4; kp++) {
            unsigned pb0 = pack2(s[2*kp  ][0], s[2*kp  ][1]);
            unsigned pb1 = pack2(s[2*kp  ][2], s[2*kp  ][3]);
            unsigned pb2 = pack2(s[2*kp+1][0], s[2*kp+1][1]);
            unsigned pb3 = pack2(s[2*kp+1][2], s[2*kp+1][3]);
            #pragma unroll
            for (int jn = 0; jn < 8; jn++) {
                const int vbo = (jn*8+g)*PCH + kp*8 + q*2;
                uint2 vb = *(const uint2*)&Vb[vbo];
                mma16816(oacc[jn][0],oacc[jn][1],oacc[jn][2],oacc[jn][3],
                         pb0,pb1,pb2,pb3, vb.x,vb.y);
            }
        }
        __syncthreads();
        stg ^= 1;
    }

    float* Og = g_po[kh] + ((size_t)b*T + q0)*DHEAD;
    #pragma unroll
    for (int jn = 0; jn < 8; jn++) {
        int col = jn*8 + q*2;
        int r0 = wrow + g;
        *(float2*)&Og[(size_t)r0*DHEAD + col]     = make_float2(oacc[jn][0], oacc[jn][1]);
        *(float2*)&Og[(size_t)(r0+8)*DHEAD + col] = make_float2(oacc[jn][2], oacc[jn][3]);
    }
    if (q == 0) {
        g_pl[kh][(size_t)b*T + q0 + wrow + g]     = l0;
        g_pl[kh][(size_t)b*T + q0 + wrow + 8 + g] = l1;
    }
    #undef ISSUE
}

// ---------------------------------------------------------------------------
// Kernel 3: merge split-K partials. out = (Oa + Ob) / (la + lb).
// ---------------------------------------------------------------------------
__global__ __launch_bounds__(256) void merge_kernel(float* __restrict__ out)
{
    const int idx4 = blockIdx.x * 256 + threadIdx.x;
    const size_t base = (size_t)idx4 * 4;
    const int row = (int)(base >> 6);
    float4 a = *(const float4*)&g_po[0][base];
    float4 b = *(const float4*)&g_po[1][base];
    float inv = 1.f / (g_pl[0][row] + g_pl[1][row]);
    float4 o;
    o.x = (a.x + b.x) * inv;
    o.y = (a.y + b.y) * inv;
    o.z = (a.z + b.z) * inv;
    o.w = (a.w + b.w) * inv;
    *(float4*)&out[base] = o;
}

// ---------------------------------------------------------------------------
extern "C" void kernel_launch(void* const* d_in, const int* in_sizes, int n_in,
                              void* d_out, int out_size)
{
    const float* x  = (const float*)d_in[0];
    const float* Wk = (const float*)d_in[1];
    const float* bk = (const float*)d_in[2];
    const float* Wq = (const float*)d_in[3];
    const float* bq = (const float*)d_in[4];
    const float* Wv = (const float*)d_in[5];
    const float* bv = (const float*)d_in[6];
    float* out = (float*)d_out;

    cudaFuncSetAttribute(qkv_kernel,
                         cudaFuncAttributeMaxDynamicSharedMemorySize, QKV_SMEM);
    cudaFuncSetAttribute(attn_kernel,
                         cudaFuncAttributeMaxDynamicSharedMemorySize, ATTN_SMEM);

    qkv_kernel<<<MT/128, 256, QKV_SMEM>>>(x, Wk, bk, Wq, bq, Wv, bv);

    dim3 g2(T / 128, NB, 2);
    attn_kernel<<<g2, 256, ATTN_SMEM>>>();

    merge_kernel<<<(MT*DHEAD/4)/256, 256>>>(out);
}